// round 16
// baseline (speedup 1.0000x reference)
#include <cuda_runtime.h>
#include <cstdint>

// BoundarySeg: out[b,j,0:768]   = sum_{d=0..5} w[b,j,d] * hidden[b, min(j+d,L-1), :]
//              out[b,j,768:1536]= hidden[b,j,:] * sum_d w[b,j,d]
// w[b,j,d] = span_adjacency[b, j, j+d] if j+d < L else 0.
// B=16, L=1024, H=768. fp32.
//
// R16: last point on the only validated gradient — tile height.
// TJ: 8 -> 22.1us, 16 -> 21.4us; now TJ=32 (read amplification 1.16x,
// 512 CTAs, one 111KB TMA per CTA, 2 CTAs/SM). Skeleton unchanged from the
// best kernel: TMA bulk-in, 6-row sliding register window from smem,
// streaming .cs STG.128 out. Roofline: ~96MB output writes @ ~4.4TB/s.

#define BB 16
#define LL 1024
#define HH 768
#define HV (HH / 4)            // 192 float4 per row
#define TJ 32                  // j's per CTA
#define SPAN 6
#define NROWS (TJ + SPAN - 1)  // 37 rows staged

struct __align__(16) SmemLayout {
    float4   in[NROWS * HV];     // 113664 B
    float    w[TJ * SPAN];       // 768 B
    uint64_t mbar;
};

__device__ __forceinline__ uint32_t smem_u32(const void* p) {
    uint32_t a;
    asm("{ .reg .u64 t; cvta.to.shared.u64 t, %1; cvt.u32.u64 %0, t; }"
        : "=r"(a) : "l"(p));
    return a;
}

__device__ __forceinline__ void stcs4(float4* p, float4 v) {
    asm volatile("st.global.cs.v4.f32 [%0], {%1,%2,%3,%4};"
                 :: "l"(p), "f"(v.x), "f"(v.y), "f"(v.z), "f"(v.w) : "memory");
}

__global__ __launch_bounds__(HV)
void boundary_seg_kernel(const float* __restrict__ adj,
                         const float* __restrict__ hid,
                         float* __restrict__ out)
{
    extern __shared__ __align__(16) char smem_raw[];
    SmemLayout* sm = reinterpret_cast<SmemLayout*>(smem_raw);

    const int tile = blockIdx.x;           // b * 32 + jt
    const int b  = tile >> 5;
    const int j0 = (tile & 31) * TJ;
    const int t  = threadIdx.x;            // float4 column of H

    const int rl = min(NROWS, LL - j0);    // rows actually available
    const uint32_t in_bytes = (uint32_t)rl * HH * 4u;

    const uint32_t s_in   = smem_u32(sm->in);
    const uint32_t s_mbar = smem_u32(&sm->mbar);

    if (t == 0) {
        asm volatile("mbarrier.init.shared::cta.b64 [%0], %1;"
                     :: "r"(s_mbar), "r"(1) : "memory");
    }
    __syncthreads();

    if (t == 0) {
        asm volatile("mbarrier.arrive.expect_tx.shared::cta.b64 _, [%0], %1;"
                     :: "r"(s_mbar), "r"(in_bytes) : "memory");
        const float* src = hid + ((size_t)b * LL + j0) * HH;
        asm volatile(
            "cp.async.bulk.shared::cluster.global.mbarrier::complete_tx::bytes "
            "[%0], [%1], %2, [%3];"
            :: "r"(s_in), "l"(src), "r"(in_bytes), "r"(s_mbar) : "memory");
    }

    // Weights: 192 scattered L2 loads (one per thread), overlapped with TMA.
    {
        const int jj = t / SPAN;           // t < 192 = 32*6 exactly
        const int d  = t - jj * SPAN;
        const int col = j0 + jj + d;
        float w = 0.0f;
        if (col < LL)
            w = __ldg(adj + ((size_t)b * LL + (j0 + jj)) * LL + col);
        sm->w[jj * SPAN + d] = w;
    }
    __syncthreads();

    // Wait for the TMA bulk copy.
    {
        uint32_t done;
        do {
            asm volatile(
                "{ .reg .pred p;\n\t"
                "  mbarrier.try_wait.parity.shared::cta.b64 p, [%1], %2, 10000000;\n\t"
                "  selp.b32 %0, 1, 0, p; }"
                : "=r"(done) : "r"(s_mbar), "r"(0u) : "memory");
        } while (!done);
    }

    const int rmax = rl - 1;

    // Sliding register window of 6 rows (this thread's float4 column).
    float4 v[SPAN];
#pragma unroll
    for (int d = 0; d < SPAN; d++)
        v[d] = sm->in[min(d, rmax) * HV + t];

    float4* __restrict__ out4 = reinterpret_cast<float4*>(out);

#pragma unroll
    for (int jj = 0; jj < TJ; jj++) {
        const float w0 = sm->w[jj * SPAN + 0], w1 = sm->w[jj * SPAN + 1];
        const float w2 = sm->w[jj * SPAN + 2], w3 = sm->w[jj * SPAN + 3];
        const float w4 = sm->w[jj * SPAN + 4], w5 = sm->w[jj * SPAN + 5];
        const float wsum = ((w0 + w1) + (w2 + w3)) + (w4 + w5);

        float4 f;
        f.x = w0 * v[0].x; f.y = w0 * v[0].y;
        f.z = w0 * v[0].z; f.w = w0 * v[0].w;
        f.x = fmaf(w1, v[1].x, f.x); f.y = fmaf(w1, v[1].y, f.y);
        f.z = fmaf(w1, v[1].z, f.z); f.w = fmaf(w1, v[1].w, f.w);
        f.x = fmaf(w2, v[2].x, f.x); f.y = fmaf(w2, v[2].y, f.y);
        f.z = fmaf(w2, v[2].z, f.z); f.w = fmaf(w2, v[2].w, f.w);
        f.x = fmaf(w3, v[3].x, f.x); f.y = fmaf(w3, v[3].y, f.y);
        f.z = fmaf(w3, v[3].z, f.z); f.w = fmaf(w3, v[3].w, f.w);
        f.x = fmaf(w4, v[4].x, f.x); f.y = fmaf(w4, v[4].y, f.y);
        f.z = fmaf(w4, v[4].z, f.z); f.w = fmaf(w4, v[4].w, f.w);
        f.x = fmaf(w5, v[5].x, f.x); f.y = fmaf(w5, v[5].y, f.y);
        f.z = fmaf(w5, v[5].z, f.z); f.w = fmaf(w5, v[5].w, f.w);

        float4 s;
        s.x = v[0].x * wsum; s.y = v[0].y * wsum;
        s.z = v[0].z * wsum; s.w = v[0].w * wsum;

        const size_t obase = ((size_t)b * LL + (j0 + jj)) * (size_t)(2 * HV);
        stcs4(out4 + obase + t, f);
        stcs4(out4 + obase + HV + t, s);

        // Slide the window.
#pragma unroll
        for (int d = 0; d < SPAN - 1; d++) v[d] = v[d + 1];
        v[SPAN - 1] = sm->in[min(jj + SPAN, rmax) * HV + t];
    }
}

extern "C" void kernel_launch(void* const* d_in, const int* in_sizes, int n_in,
                              void* d_out, int out_size)
{
    const float* adj = (const float*)d_in[0];   // (B,L,L,1)
    const float* hid = (const float*)d_in[1];   // (B,L,H)
    float* out = (float*)d_out;                 // (B,L,2H)

    const int smem_bytes = (int)sizeof(SmemLayout);
    static bool attr_set = false;
    if (!attr_set) {
        cudaFuncSetAttribute(boundary_seg_kernel,
                             cudaFuncAttributeMaxDynamicSharedMemorySize,
                             smem_bytes);
        attr_set = true;
    }

    const int grid = BB * (LL / TJ);            // 512 CTAs
    boundary_seg_kernel<<<grid, HV, smem_bytes>>>(adj, hid, out);
}

// round 17
// speedup vs baseline: 1.0189x; 1.0189x over previous
#include <cuda_runtime.h>
#include <cstdint>

// BoundarySeg: out[b,j,0:768]   = sum_{d=0..5} w[b,j,d] * hidden[b, min(j+d,L-1), :]
//              out[b,j,768:1536]= hidden[b,j,:] * sum_d w[b,j,d]
// w[b,j,d] = span_adjacency[b, j, j+d] if j+d < L else 0.
// B=16, L=1024, H=768. fp32.
//
// R17: proven-optimal TJ=16 tile (TMA bulk-in + sliding smem window +
// streaming .cs STG), now with 384 threads per CTA: warpgroup 0 computes
// j 0..7, warpgroup 1 computes j 8..15 concurrently from the shared 21-row
// buffer. Doubles independent store streams per CTA and halves each CTA's
// serial store epilogue; read traffic / smem / TMA identical to the best
// measured kernel (21.38us).

#define BB 16
#define LL 1024
#define HH 768
#define HV (HH / 4)            // 192 float4 per row
#define TJ 16                  // j's per CTA
#define HALF 8                 // j's per warpgroup
#define SPAN 6
#define NROWS (TJ + SPAN - 1)  // 21 rows staged
#define NTHREADS (2 * HV)      // 384

struct __align__(16) SmemLayout {
    float4   in[NROWS * HV];     // 64512 B
    float    w[TJ * SPAN];       // 384 B
    uint64_t mbar;
};

__device__ __forceinline__ uint32_t smem_u32(const void* p) {
    uint32_t a;
    asm("{ .reg .u64 t; cvta.to.shared.u64 t, %1; cvt.u32.u64 %0, t; }"
        : "=r"(a) : "l"(p));
    return a;
}

__device__ __forceinline__ void stcs4(float4* p, float4 v) {
    asm volatile("st.global.cs.v4.f32 [%0], {%1,%2,%3,%4};"
                 :: "l"(p), "f"(v.x), "f"(v.y), "f"(v.z), "f"(v.w) : "memory");
}

__global__ __launch_bounds__(NTHREADS)
void boundary_seg_kernel(const float* __restrict__ adj,
                         const float* __restrict__ hid,
                         float* __restrict__ out)
{
    extern __shared__ __align__(16) char smem_raw[];
    SmemLayout* sm = reinterpret_cast<SmemLayout*>(smem_raw);

    const int tile = blockIdx.x;           // b * 64 + jt
    const int b  = tile >> 6;
    const int j0 = (tile & 63) * TJ;
    const int t  = threadIdx.x;
    const int h  = t / HV;                 // warpgroup: 0 -> j 0..7, 1 -> j 8..15
    const int c  = t - h * HV;             // float4 column of H

    const int rl = min(NROWS, LL - j0);    // 21, or 16 on the last tile of b
    const uint32_t in_bytes = (uint32_t)rl * HH * 4u;

    const uint32_t s_in   = smem_u32(sm->in);
    const uint32_t s_mbar = smem_u32(&sm->mbar);

    if (t == 0) {
        asm volatile("mbarrier.init.shared::cta.b64 [%0], %1;"
                     :: "r"(s_mbar), "r"(1) : "memory");
    }
    __syncthreads();

    if (t == 0) {
        asm volatile("mbarrier.arrive.expect_tx.shared::cta.b64 _, [%0], %1;"
                     :: "r"(s_mbar), "r"(in_bytes) : "memory");
        const float* src = hid + ((size_t)b * LL + j0) * HH;
        asm volatile(
            "cp.async.bulk.shared::cluster.global.mbarrier::complete_tx::bytes "
            "[%0], [%1], %2, [%3];"
            :: "r"(s_in), "l"(src), "r"(in_bytes), "r"(s_mbar) : "memory");
    }

    // Weights: 96 scattered L2 loads by the first 96 threads, overlapped
    // with the TMA.
    if (t < TJ * SPAN) {
        const int jj = t / SPAN;
        const int d  = t - jj * SPAN;
        const int col = j0 + jj + d;
        float w = 0.0f;
        if (col < LL)
            w = __ldg(adj + ((size_t)b * LL + (j0 + jj)) * LL + col);
        sm->w[jj * SPAN + d] = w;
    }
    __syncthreads();

    // Wait for the TMA bulk copy (all threads; cheap try_wait spin).
    {
        uint32_t done;
        do {
            asm volatile(
                "{ .reg .pred p;\n\t"
                "  mbarrier.try_wait.parity.shared::cta.b64 p, [%1], %2, 10000000;\n\t"
                "  selp.b32 %0, 1, 0, p; }"
                : "=r"(done) : "r"(s_mbar), "r"(0u) : "memory");
        } while (!done);
    }

    const int rmax = rl - 1;
    const int jbase = h * HALF;            // 0 or 8

    // Sliding register window of 6 rows for this warpgroup's j range.
    float4 v[SPAN];
#pragma unroll
    for (int d = 0; d < SPAN; d++)
        v[d] = sm->in[min(jbase + d, rmax) * HV + c];

    float4* __restrict__ out4 = reinterpret_cast<float4*>(out);

#pragma unroll
    for (int e = 0; e < HALF; e++) {
        const int jj = jbase + e;
        const float w0 = sm->w[jj * SPAN + 0], w1 = sm->w[jj * SPAN + 1];
        const float w2 = sm->w[jj * SPAN + 2], w3 = sm->w[jj * SPAN + 3];
        const float w4 = sm->w[jj * SPAN + 4], w5 = sm->w[jj * SPAN + 5];
        const float wsum = ((w0 + w1) + (w2 + w3)) + (w4 + w5);

        float4 f;
        f.x = w0 * v[0].x; f.y = w0 * v[0].y;
        f.z = w0 * v[0].z; f.w = w0 * v[0].w;
        f.x = fmaf(w1, v[1].x, f.x); f.y = fmaf(w1, v[1].y, f.y);
        f.z = fmaf(w1, v[1].z, f.z); f.w = fmaf(w1, v[1].w, f.w);
        f.x = fmaf(w2, v[2].x, f.x); f.y = fmaf(w2, v[2].y, f.y);
        f.z = fmaf(w2, v[2].z, f.z); f.w = fmaf(w2, v[2].w, f.w);
        f.x = fmaf(w3, v[3].x, f.x); f.y = fmaf(w3, v[3].y, f.y);
        f.z = fmaf(w3, v[3].z, f.z); f.w = fmaf(w3, v[3].w, f.w);
        f.x = fmaf(w4, v[4].x, f.x); f.y = fmaf(w4, v[4].y, f.y);
        f.z = fmaf(w4, v[4].z, f.z); f.w = fmaf(w4, v[4].w, f.w);
        f.x = fmaf(w5, v[5].x, f.x); f.y = fmaf(w5, v[5].y, f.y);
        f.z = fmaf(w5, v[5].z, f.z); f.w = fmaf(w5, v[5].w, f.w);

        float4 s;
        s.x = v[0].x * wsum; s.y = v[0].y * wsum;
        s.z = v[0].z * wsum; s.w = v[0].w * wsum;

        const size_t obase = ((size_t)b * LL + (j0 + jj)) * (size_t)(2 * HV);
        stcs4(out4 + obase + c, f);
        stcs4(out4 + obase + HV + c, s);

        // Slide the window.
#pragma unroll
        for (int d = 0; d < SPAN - 1; d++) v[d] = v[d + 1];
        v[SPAN - 1] = sm->in[min(jj + SPAN, rmax) * HV + c];
    }
}

extern "C" void kernel_launch(void* const* d_in, const int* in_sizes, int n_in,
                              void* d_out, int out_size)
{
    const float* adj = (const float*)d_in[0];   // (B,L,L,1)
    const float* hid = (const float*)d_in[1];   // (B,L,H)
    float* out = (float*)d_out;                 // (B,L,2H)

    const int smem_bytes = (int)sizeof(SmemLayout);
    static bool attr_set = false;
    if (!attr_set) {
        cudaFuncSetAttribute(boundary_seg_kernel,
                             cudaFuncAttributeMaxDynamicSharedMemorySize,
                             smem_bytes);
        attr_set = true;
    }

    const int grid = BB * (LL / TJ);            // 1024 CTAs
    boundary_seg_kernel<<<grid, NTHREADS, smem_bytes>>>(adj, hid, out);
}